// round 7
// baseline (speedup 1.0000x reference)
#include <cuda_runtime.h>

// SpanRepLayer, fused: smem token slab + smem M3 pyramid, quarter channel split.
// B=8, K=2048, S=1024, H=256, W=24, WIN=3.

constexpr int Bc = 8;
constexpr int Kc = 2048;
constexpr int Sc = 1024;
constexpr int WINc = 3;

constexpr int TT = 32;          // span-start tile
constexpr int NT = Sc / TT;     // 32 tiles
constexpr int R0 = 56;          // token rows resident (max queried row t0+54)
constexpr int R3 = 53;          // M3 rows (max queried idx t0+52)
constexpr int C4 = 16;          // float4 per row (64-channel quarter)
constexpr int LISTCAP = 192;    // mean ~65 spans/tile

__device__ __forceinline__ float4 f4max(float4 a, float4 b) {
    return make_float4(fmaxf(a.x, b.x), fmaxf(a.y, b.y),
                       fmaxf(a.z, b.z), fmaxf(a.w, b.w));
}

__global__ __launch_bounds__(256, 8)
void span_fused(const float* __restrict__ tok,
                const int* __restrict__ ids,
                const int* __restrict__ masks,   // bool widened to int32
                float* __restrict__ out)
{
    extern __shared__ float4 sm[];
    float4* T0 = sm;                       // R0*C4
    float4* M3 = sm + R0 * C4;             // R3*C4
    __shared__ int4 list[LISTCAP];         // (k, s, e, mask)
    __shared__ int nspan;

    const int tid  = threadIdx.x;
    const int q    = blockIdx.x & 3;             // channel quarter
    const int tile = (blockIdx.x >> 2) & (NT - 1);
    const int b    = blockIdx.x >> 7;
    const int t0   = tile * TT;

    if (tid == 0) nspan = 0;
    __syncthreads();

    // ---- load token slab (rows [t0, t0+56), this block's 64 channels) ----
    const float4* g = reinterpret_cast<const float4*>(tok)
                    + (size_t)b * Sc * 64 + q * C4;
    #pragma unroll
    for (int j = 0; j < (R0 * C4 + 255) / 256; j++) {
        const int i = tid + j * 256;
        if (i < R0 * C4) {
            const int r = i >> 4, c = i & 15;
            T0[i] = __ldg(g + (size_t)min(t0 + r, Sc - 1) * 64 + c);
        }
    }

    // ---- scan batch spans; compact (k,s,e,mask) for starts in our tile ----
    #pragma unroll
    for (int j = 0; j < Kc / 256; j++) {
        const int k = tid + j * 256;
        const int2 se = __ldg(reinterpret_cast<const int2*>(ids) + b * Kc + k);
        if ((se.x >> 5) == tile) {
            const int m = __ldg(masks + b * Kc + k);
            const int p = atomicAdd(&nspan, 1);
            if (p < LISTCAP) list[p] = make_int4(k, se.x, se.y, m);
        }
    }
    __syncthreads();

    // ---- build M3[r] = max(T0[r..r+2]) ----
    #pragma unroll
    for (int j = 0; j < (R3 * C4 + 255) / 256; j++) {
        const int i = tid + j * 256;
        if (i < R3 * C4)
            M3[i] = f4max(f4max(T0[i], T0[i + C4]), T0[i + 2 * C4]);
    }
    __syncthreads();

    // ---- per-half-warp span processing: pure smem + STG ----
    const int wid = tid >> 5, lane = tid & 31;
    const int hw  = lane >> 4, li = lane & 15;   // half-warp id, lane-in-half
    const int n = min(nspan, LISTCAP);

    for (int i = wid * 2 + hw; i < n; i += 16) { // 8 warps x 2 spans each
        const int4 sp = list[i];
        float4* o = reinterpret_cast<float4*>(out)
                  + (size_t)(b * Kc + sp.x) * 192 + q * C4 + li;

        if (sp.w == 0) {
            const float4 z = make_float4(0.f, 0.f, 0.f, 0.f);
            o[0] = z; o[64] = z; o[128] = z;
            continue;
        }

        const int ls = sp.y - t0;          // [0,32)
        const int le = sp.z - t0;          // <= 55
        const int w  = le - ls;

        float4 S, E;
        if (w >= 3)      { S = M3[ls * C4 + li]; E = M3[(le - 3) * C4 + li]; }
        else if (w == 2) { S = f4max(T0[ls * C4 + li], T0[(ls + 1) * C4 + li]); E = S; }
        else             { S = T0[ls * C4 + li]; E = S; }

        const int wp = w - 2 * WINc;       // inner width (<=18)
        const int a  = ls + WINc;
        float4 I;
        if (wp <= 0)      I = S;                                   // all--inf fallback
        else if (wp == 1) I = T0[a * C4 + li];
        else if (wp == 2) I = f4max(T0[a * C4 + li], T0[(a + 1) * C4 + li]);
        else {
            I = M3[(a + wp - 3) * C4 + li];
            for (int p = a; p < a + wp - 3; p += 3)                // <=5 iters
                I = f4max(I, M3[p * C4 + li]);
        }

        o[0] = S; o[64] = I; o[128] = E;
    }
}

extern "C" void kernel_launch(void* const* d_in, const int* in_sizes, int n_in,
                              void* d_out, int out_size)
{
    const float* tok   = (const float*)d_in[0];
    const int*   ids   = (const int*)d_in[1];
    const int*   masks = (const int*)d_in[2];
    float*       out   = (float*)d_out;

    constexpr int SMEM = (R0 + R3) * C4 * (int)sizeof(float4);   // 27904 B
    cudaFuncSetAttribute(span_fused, cudaFuncAttributeMaxDynamicSharedMemorySize, SMEM);

    span_fused<<<Bc * NT * 4, 256, SMEM>>>(tok, ids, masks, out);  // 1024 blocks
}